// round 15
// baseline (speedup 1.0000x reference)
#include <cuda_runtime.h>

#define W 224
#define WW (W * W)                  // 50176
#define F8_PER (WW / 8)             // 6272 float8 per sample
#define F8_PER_ROW (W / 8)          // 28
#define NSAMP 256
#define BLK_PER_SAMP 7
#define NBLK1 (NSAMP * BLK_PER_SAMP)        // 1792
#define F8_PER_BLK (F8_PER / BLK_PER_SAMP)  // 896 f8 = 32 rows per chunk
#define NBLK2 NBLK1
#define NTHREADS 128                        // 4 warps: 16 CTA/SM -> whole grid resident
#define ITERS (F8_PER_BLK / NTHREADS)       // 7
#define LN2 0.6931471805599453

// Scratch (device globals; zero-init at load; g_acc/g_cnt reset by last block)
__device__ int4     g_blk[NBLK1];   // per-block {maxbits, cnt, si, sj}
__device__ double   g_acc;
__device__ unsigned g_cnt;

__device__ __forceinline__ float fast_lg2(float x) {
    float r; asm("lg2.approx.f32 %0, %1;" : "=f"(r) : "f"(x)); return r;
}
__device__ __forceinline__ float fast_sqrt(float x) {
    float r; asm("sqrt.approx.f32 %0, %1;" : "=f"(r) : "f"(x)); return r;
}
__device__ __forceinline__ float fast_rcp(float x) {
    float r; asm("rcp.approx.f32 %0, %1;" : "=f"(r) : "f"(x)); return r;
}

struct F8 { float v[8]; };

__device__ __forceinline__ F8 unpack8(unsigned long long x0, unsigned long long x1,
                                      unsigned long long x2, unsigned long long x3) {
    F8 r;
    r.v[0] = __uint_as_float((unsigned)(x0)); r.v[1] = __uint_as_float((unsigned)(x0 >> 32));
    r.v[2] = __uint_as_float((unsigned)(x1)); r.v[3] = __uint_as_float((unsigned)(x1 >> 32));
    r.v[4] = __uint_as_float((unsigned)(x2)); r.v[5] = __uint_as_float((unsigned)(x2 >> 32));
    r.v[6] = __uint_as_float((unsigned)(x3)); r.v[7] = __uint_as_float((unsigned)(x3 >> 32));
    return r;
}

// target: read twice per replay -> protect in L2 (harmless if ignored).
__device__ __forceinline__ F8 ldg_keep8(const float* p) {
    unsigned long long x0, x1, x2, x3;
    asm("ld.global.L2::evict_last.v4.b64 {%0,%1,%2,%3}, [%4];"
        : "=l"(x0), "=l"(x1), "=l"(x2), "=l"(x3) : "l"(p));
    return unpack8(x0, x1, x2, x3);
}
// input: read once per replay -> stream.
__device__ __forceinline__ F8 ldg_stream8(const float* p) {
    unsigned long long x0, x1, x2, x3;
    asm("ld.global.L2::evict_first.v4.b64 {%0,%1,%2,%3}, [%4];"
        : "=l"(x0), "=l"(x1), "=l"(x2), "=l"(x3) : "l"(p));
    return unpack8(x0, x1, x2, x3);
}

// ---------------------------------------------------------------------------
// Kernel 1: per-block max + tie stats, one pass, ties counted from registers.
// grid = 1792 (7 blocks/sample), 128 threads, 7 float8 per thread.
// ---------------------------------------------------------------------------
__global__ __launch_bounds__(NTHREADS) void k_maxstats(const float* __restrict__ tgt) {
    const int b = blockIdx.x / BLK_PER_SAMP;
    const int c = blockIdx.x - b * BLK_PER_SAMP;
    const int tid = threadIdx.x;
    const float* __restrict__ tb =
        tgt + (size_t)b * WW + (size_t)c * F8_PER_BLK * 8;

    F8 v[ITERS];
    #pragma unroll
    for (int k = 0; k < ITERS; k++) v[k] = ldg_keep8(tb + (k * NTHREADS + tid) * 8);

    float tmax = -3.0e38f;
    #pragma unroll
    for (int k = 0; k < ITERS; k++)
        #pragma unroll
        for (int e = 0; e < 8; e++) tmax = fmaxf(tmax, v[k].v[e]);

    float m = tmax;
    #pragma unroll
    for (int o = 16; o > 0; o >>= 1)
        m = fmaxf(m, __shfl_xor_sync(0xffffffffu, m, o));

    __shared__ float smax[4];
    __shared__ float sM;
    __shared__ int scnt, ssi, ssj;
    const int wid = tid >> 5, lid = tid & 31;
    if (lid == 0) smax[wid] = m;
    if (tid == 0) { scnt = 0; ssi = 0; ssj = 0; }
    __syncthreads();
    if (tid == 0) {
        sM = fmaxf(fmaxf(smax[0], smax[1]), fmaxf(smax[2], smax[3]));
    }
    __syncthreads();
    const float M = sM;

    if (tmax == M) {   // rare: only threads holding the block max
        int cnt = 0, si = 0, sj = 0;
        #pragma unroll
        for (int k = 0; k < ITERS; k++) {
            const int r8 = c * F8_PER_BLK + k * NTHREADS + tid;  // f8 idx in sample
            const int i  = r8 / F8_PER_ROW;
            const int j0 = (r8 - i * F8_PER_ROW) * 8;
            #pragma unroll
            for (int e = 0; e < 8; e++)
                if (v[k].v[e] == M) { cnt++; si += i; sj += j0 + e; }
        }
        atomicAdd_block(&scnt, cnt);
        atomicAdd_block(&ssi,  si);
        atomicAdd_block(&ssj,  sj);
    }
    __syncthreads();

    if (tid == 0) {
        const unsigned mb = __float_as_uint(M);   // target >= 0 -> bit order == float order
        g_blk[blockIdx.x] = make_int4((int)mb, scnt, ssi, ssj);
    }
}

// ---------------------------------------------------------------------------
// Kernel 2: weighted BCE. grid = (7, 256), 128 threads, 7 float8 per thread.
// i,j derived per-iteration via constant div by 28 (umulhi) — cost amortized
// over 8 elements. Whole grid resident in one wave.
// ---------------------------------------------------------------------------
__global__ __launch_bounds__(NTHREADS) void k_loss(const float* __restrict__ inp,
                                                   const float* __restrict__ tgt,
                                                   float* __restrict__ out,
                                                   double scale) {
    const int samp = blockIdx.y;
    const int c    = blockIdx.x;
    const int tid  = threadIdx.x;

    __shared__ float2 sxy;
    if (tid == 0) {
        int4 e[BLK_PER_SAMP];
        #pragma unroll
        for (int q = 0; q < BLK_PER_SAMP; q++) e[q] = g_blk[samp * BLK_PER_SAMP + q];
        unsigned mb = 0u;
        #pragma unroll
        for (int q = 0; q < BLK_PER_SAMP; q++) mb = max(mb, (unsigned)e[q].x);
        int cnt = 0, si = 0, sj = 0;
        #pragma unroll
        for (int q = 0; q < BLK_PER_SAMP; q++)
            if ((unsigned)e[q].x == mb) { cnt += e[q].y; si += e[q].z; sj += e[q].w; }
        const float inv = 1.0f / (float)cnt;
        sxy = make_float2((float)si * inv, (float)sj * inv);
    }
    __syncthreads();
    const float cx = sxy.x, cy = sxy.y;

    const float* __restrict__ pb = inp + (size_t)samp * WW + (size_t)c * F8_PER_BLK * 8;
    const float* __restrict__ tb = tgt + (size_t)samp * WW + (size_t)c * F8_PER_BLK * 8;

    float s = 0.0f;

    // software pipeline: loads for k+1 in flight while processing k
    F8 pv = ldg_stream8(pb + tid * 8);
    F8 tv = ldg_keep8(tb + tid * 8);
    #pragma unroll
    for (int k = 0; k < ITERS; k++) {
        F8 pn, tn;
        if (k < ITERS - 1) {
            pn = ldg_stream8(pb + ((k + 1) * NTHREADS + tid) * 8);
            tn = ldg_keep8(tb + ((k + 1) * NTHREADS + tid) * 8);
        }

        // per-f8 index math (amortized over 8 elements)
        const int r8 = c * F8_PER_BLK + k * NTHREADS + tid;   // f8 idx in sample
        const int i  = r8 / F8_PER_ROW;                       // umulhi const-div
        const int j0 = (r8 - i * F8_PER_ROW) * 8;
        const float di  = (float)i - cx;
        const float di2 = di * di;
        const float dj0 = (float)j0 - cy;

        #pragma unroll
        for (int e = 0; e < 8; e++) {
            float dj  = dj0 + (float)e;
            float d2  = fmaf(dj, dj, di2);
            float wr  = fast_rcp(fast_sqrt(d2) + 1.0f);   // 1/(sqrt(d2)+1)
            float lp2 = fast_lg2(pv.v[e]);                // log2 p
            float lq2 = fast_lg2(1.0f - pv.v[e]);         // log2 (1-p)
            float bce = fmaf(tv.v[e], lq2 - lp2, -lq2);   // -(t lp + (1-t) lq), log2 units
            s = fmaf(wr, bce, s);
        }
        pv = pn; tv = tn;
    }

    #pragma unroll
    for (int o = 16; o > 0; o >>= 1)
        s += __shfl_xor_sync(0xffffffffu, s, o);

    __shared__ float sw[4];
    const int wid = tid >> 5, lid = tid & 31;
    if (lid == 0) sw[wid] = s;
    __syncthreads();
    if (tid == 0) {
        float bs = (sw[0] + sw[1]) + (sw[2] + sw[3]);
        atomicAdd(&g_acc, (double)bs);
        __threadfence();
        const unsigned ticket = atomicAdd(&g_cnt, 1u);
        if (ticket == NBLK2 - 1) {          // last block: finalize + reset
            const double total = atomicAdd(&g_acc, 0.0);
            out[0] = (float)(total * scale);
            g_acc = 0.0;
            g_cnt = 0u;
        }
    }
}

extern "C" void kernel_launch(void* const* d_in, const int* in_sizes, int n_in,
                              void* d_out, int out_size) {
    const float* inp = (const float*)d_in[0];
    const float* tgt = (const float*)d_in[1];
    float* out = (float*)d_out;

    k_maxstats<<<NBLK1, NTHREADS>>>(tgt);
    dim3 g2(BLK_PER_SAMP, NSAMP);
    // scale = W * ln2 / N  (W: weight numerator; ln2: log2->ln; 1/N: mean)
    const double scale = (double)W * LN2 / (double)((size_t)NSAMP * WW);
    k_loss<<<g2, NTHREADS>>>(inp, tgt, out, scale);
}

// round 16
// speedup vs baseline: 1.0920x; 1.0920x over previous
#include <cuda_runtime.h>

#define W 224
#define WW (W * W)                  // 50176
#define F8_PER (WW / 8)             // 6272 float8 per sample
#define F8_PER_ROW (W / 8)          // 28
#define NSAMP 256
#define BLK_PER_SAMP 7
#define NBLK1 (NSAMP * BLK_PER_SAMP)        // 1792
#define F8_PER_BLK (F8_PER / BLK_PER_SAMP)  // 896 f8 = 32 rows per chunk
#define NBLK2 NBLK1
#define NTHREADS 224                        // 8 rows x 28 f8; ITERS=4, no spills
#define ITERS (F8_PER_BLK / NTHREADS)       // 4
#define LN2 0.6931471805599453

// Scratch (device globals; zero-init at load; g_acc/g_cnt reset by last block)
__device__ int4     g_blk[NBLK1];   // per-block {maxbits, cnt, si, sj}
__device__ double   g_acc;
__device__ unsigned g_cnt;

__device__ __forceinline__ float fast_lg2(float x) {
    float r; asm("lg2.approx.f32 %0, %1;" : "=f"(r) : "f"(x)); return r;
}
__device__ __forceinline__ float fast_sqrt(float x) {
    float r; asm("sqrt.approx.f32 %0, %1;" : "=f"(r) : "f"(x)); return r;
}
__device__ __forceinline__ float fast_rcp(float x) {
    float r; asm("rcp.approx.f32 %0, %1;" : "=f"(r) : "f"(x)); return r;
}

struct F8 { float v[8]; };

__device__ __forceinline__ F8 unpack8(unsigned long long x0, unsigned long long x1,
                                      unsigned long long x2, unsigned long long x3) {
    F8 r;
    r.v[0] = __uint_as_float((unsigned)(x0)); r.v[1] = __uint_as_float((unsigned)(x0 >> 32));
    r.v[2] = __uint_as_float((unsigned)(x1)); r.v[3] = __uint_as_float((unsigned)(x1 >> 32));
    r.v[4] = __uint_as_float((unsigned)(x2)); r.v[5] = __uint_as_float((unsigned)(x2 >> 32));
    r.v[6] = __uint_as_float((unsigned)(x3)); r.v[7] = __uint_as_float((unsigned)(x3 >> 32));
    return r;
}

// target: read twice per replay -> protect in L2.
__device__ __forceinline__ F8 ldg_keep8(const float* p) {
    unsigned long long x0, x1, x2, x3;
    asm("ld.global.L2::evict_last.v4.b64 {%0,%1,%2,%3}, [%4];"
        : "=l"(x0), "=l"(x1), "=l"(x2), "=l"(x3) : "l"(p));
    return unpack8(x0, x1, x2, x3);
}
// input: read once per replay -> stream.
__device__ __forceinline__ F8 ldg_stream8(const float* p) {
    unsigned long long x0, x1, x2, x3;
    asm("ld.global.L2::evict_first.v4.b64 {%0,%1,%2,%3}, [%4];"
        : "=l"(x0), "=l"(x1), "=l"(x2), "=l"(x3) : "l"(p));
    return unpack8(x0, x1, x2, x3);
}

// ---------------------------------------------------------------------------
// Kernel 1: per-block max + tie stats, one pass, ties counted from registers.
// grid = 1792 (7 blocks/sample), 224 threads, 4 float8/thread (32 floats: fits).
// ---------------------------------------------------------------------------
__global__ __launch_bounds__(NTHREADS) void k_maxstats(const float* __restrict__ tgt) {
    const int b = blockIdx.x / BLK_PER_SAMP;
    const int c = blockIdx.x - b * BLK_PER_SAMP;
    const int tid = threadIdx.x;
    const float* __restrict__ tb =
        tgt + (size_t)b * WW + (size_t)c * F8_PER_BLK * 8;

    F8 v[ITERS];
    #pragma unroll
    for (int k = 0; k < ITERS; k++) v[k] = ldg_keep8(tb + (k * NTHREADS + tid) * 8);

    float tmax = -3.0e38f;
    #pragma unroll
    for (int k = 0; k < ITERS; k++)
        #pragma unroll
        for (int e = 0; e < 8; e++) tmax = fmaxf(tmax, v[k].v[e]);

    float m = tmax;
    #pragma unroll
    for (int o = 16; o > 0; o >>= 1)
        m = fmaxf(m, __shfl_xor_sync(0xffffffffu, m, o));

    __shared__ float smax[7];
    __shared__ float sM;
    __shared__ int scnt, ssi, ssj;
    const int wid = tid >> 5, lid = tid & 31;
    if (lid == 0) smax[wid] = m;
    if (tid == 0) { scnt = 0; ssi = 0; ssj = 0; }
    __syncthreads();
    if (tid == 0) {
        float bm = smax[0];
        #pragma unroll
        for (int w = 1; w < 7; w++) bm = fmaxf(bm, smax[w]);
        sM = bm;
    }
    __syncthreads();
    const float M = sM;

    if (tmax == M) {   // rare: only threads holding the block max
        int cnt = 0, si = 0, sj = 0;
        #pragma unroll
        for (int k = 0; k < ITERS; k++) {
            const int r8 = c * F8_PER_BLK + k * NTHREADS + tid;  // f8 idx in sample
            const int i  = r8 / F8_PER_ROW;
            const int j0 = (r8 - i * F8_PER_ROW) * 8;
            #pragma unroll
            for (int e = 0; e < 8; e++)
                if (v[k].v[e] == M) { cnt++; si += i; sj += j0 + e; }
        }
        atomicAdd_block(&scnt, cnt);
        atomicAdd_block(&ssi,  si);
        atomicAdd_block(&ssj,  sj);
    }
    __syncthreads();

    if (tid == 0) {
        const unsigned mb = __float_as_uint(M);   // target >= 0 -> bit order == float order
        g_blk[blockIdx.x] = make_int4((int)mb, scnt, ssi, ssj);
    }
}

// ---------------------------------------------------------------------------
// Kernel 2: weighted BCE. grid = (7, 256), 224 threads, 4 float8/thread.
// Per-thread layout: rq = tid/28 (row in 8-row group), cq = tid%28 (f8 col).
// Dual accumulators break the FMA chain; d2 via 1-FMA recurrence per element.
// ---------------------------------------------------------------------------
__global__ __launch_bounds__(NTHREADS) void k_loss(const float* __restrict__ inp,
                                                   const float* __restrict__ tgt,
                                                   float* __restrict__ out,
                                                   double scale) {
    const int samp = blockIdx.y;
    const int c    = blockIdx.x;
    const int tid  = threadIdx.x;

    __shared__ float2 sxy;
    if (tid == 0) {
        int4 e[BLK_PER_SAMP];
        #pragma unroll
        for (int q = 0; q < BLK_PER_SAMP; q++) e[q] = g_blk[samp * BLK_PER_SAMP + q];
        unsigned mb = 0u;
        #pragma unroll
        for (int q = 0; q < BLK_PER_SAMP; q++) mb = max(mb, (unsigned)e[q].x);
        int cnt = 0, si = 0, sj = 0;
        #pragma unroll
        for (int q = 0; q < BLK_PER_SAMP; q++)
            if ((unsigned)e[q].x == mb) { cnt += e[q].y; si += e[q].z; sj += e[q].w; }
        const float inv = 1.0f / (float)cnt;
        sxy = make_float2((float)si * inv, (float)sj * inv);
    }
    __syncthreads();
    const float cx = sxy.x, cy = sxy.y;

    // one-time index decomposition: 224 thr = 8 rows x 28 f8
    const int rq = tid / F8_PER_ROW;               // 0..7
    const int cq = tid - rq * F8_PER_ROW;          // 0..27
    const float di_base = (float)(c * 32 + rq) - cx;   // row dist at k=0
    const float dj0     = (float)(cq * 8) - cy;        // col dist at e=0
    const float two_dj0 = 2.0f * dj0;

    const float* __restrict__ pb = inp + (size_t)samp * WW + (size_t)c * F8_PER_BLK * 8;
    const float* __restrict__ tb = tgt + (size_t)samp * WW + (size_t)c * F8_PER_BLK * 8;

    float s0 = 0.0f, s1 = 0.0f;

    // software pipeline: loads for k+1 in flight while processing k
    F8 pv = ldg_stream8(pb + tid * 8);
    F8 tv = ldg_keep8(tb + tid * 8);
    #pragma unroll
    for (int k = 0; k < ITERS; k++) {
        F8 pn, tn;
        if (k < ITERS - 1) {
            pn = ldg_stream8(pb + ((k + 1) * NTHREADS + tid) * 8);
            tn = ldg_keep8(tb + ((k + 1) * NTHREADS + tid) * 8);
        }

        const float di  = di_base + (float)(8 * k);   // row advances 8 per k
        const float d2b = fmaf(di, di, dj0 * dj0);    // d2 at e=0

        #pragma unroll
        for (int e = 0; e < 8; e++) {
            // d2(e) = d2b + 2*e*dj0 + e^2  -> single FMA per element
            float d2  = fmaf((float)e, two_dj0, d2b + (float)(e * e));
            float wr  = fast_rcp(fast_sqrt(d2) + 1.0f);   // 1/(sqrt(d2)+1)
            float lp2 = fast_lg2(pv.v[e]);                // log2 p
            float lq2 = fast_lg2(1.0f - pv.v[e]);         // log2 (1-p)
            float bce = fmaf(tv.v[e], lq2 - lp2, -lq2);   // -(t lp + (1-t) lq), log2 units
            if (e & 1) s1 = fmaf(wr, bce, s1);
            else       s0 = fmaf(wr, bce, s0);
        }
        pv = pn; tv = tn;
    }

    float s = s0 + s1;
    #pragma unroll
    for (int o = 16; o > 0; o >>= 1)
        s += __shfl_xor_sync(0xffffffffu, s, o);

    __shared__ float sw[7];
    const int wid = tid >> 5, lid = tid & 31;
    if (lid == 0) sw[wid] = s;
    __syncthreads();
    if (tid == 0) {
        float bs = sw[0];
        #pragma unroll
        for (int w = 1; w < 7; w++) bs += sw[w];
        atomicAdd(&g_acc, (double)bs);
        __threadfence();
        const unsigned ticket = atomicAdd(&g_cnt, 1u);
        if (ticket == NBLK2 - 1) {          // last block: finalize + reset
            const double total = atomicAdd(&g_acc, 0.0);
            out[0] = (float)(total * scale);
            g_acc = 0.0;
            g_cnt = 0u;
        }
    }
}

extern "C" void kernel_launch(void* const* d_in, const int* in_sizes, int n_in,
                              void* d_out, int out_size) {
    const float* inp = (const float*)d_in[0];
    const float* tgt = (const float*)d_in[1];
    float* out = (float*)d_out;

    k_maxstats<<<NBLK1, NTHREADS>>>(tgt);
    dim3 g2(BLK_PER_SAMP, NSAMP);
    // scale = W * ln2 / N  (W: weight numerator; ln2: log2->ln; 1/N: mean)
    const double scale = (double)W * LN2 / (double)((size_t)NSAMP * WW);
    k_loss<<<g2, NTHREADS>>>(inp, tgt, out, scale);
}